// round 9
// baseline (speedup 1.0000x reference)
#include <cuda_runtime.h>
#include <cuda_bf16.h>
#include <mma.h>
#include <cstdint>
#include <math.h>

using namespace nvcuda;

#define NUM_C   10
#define OUT_CH  16
#define BATCH   256
#define KDIM    9216
#define NCOL    160

#define KSPLIT  72
#define KPER    128
#define KT      16
#define NSTG    8
#define NTHR    128
#define LDA     24
#define PSTRIDE (KSPLIT * NCOL)    /* 11520 */

__device__ float g_Upart[BATCH * KSPLIT * NCOL];
__device__ float g_U2[BATCH * NCOL];
__device__ __nv_bfloat16 g_Xh[BATCH * KDIM];
__device__ __nv_bfloat16 g_Xl[BATCH * KDIM];
__device__ __nv_bfloat16 g_Wh[NCOL * KDIM];
__device__ __nv_bfloat16 g_Wl[NCOL * KDIM];

__device__ __forceinline__ uint32_t smem_u32(const void* p) {
    uint32_t a;
    asm("{ .reg .u64 t; cvta.to.shared.u64 t, %1; cvt.u32.u64 %0, t; }"
        : "=r"(a) : "l"(p));
    return a;
}
__device__ __forceinline__ void cp16(uint32_t dst, const void* src) {
    asm volatile("cp.async.cg.shared.global [%0], [%1], 16;"
                 :: "r"(dst), "l"(src) : "memory");
}
__device__ __forceinline__ void cp_commit() {
    asm volatile("cp.async.commit_group;" ::: "memory");
}
__device__ __forceinline__ void cp_wait1() {
    asm volatile("cp.async.wait_group 1;" ::: "memory");
}
__device__ __forceinline__ void cp_wait0() {
    asm volatile("cp.async.wait_group 0;" ::: "memory");
}
/* packed fp32 -> bf16 hi/lo split */
__device__ __forceinline__ void cvt_split2(float a, float b,
                                           uint32_t& hi2, uint32_t& lo2) {
    asm("cvt.rn.bf16x2.f32 %0, %1, %2;" : "=r"(hi2) : "f"(b), "f"(a));
    float fa = __uint_as_float(hi2 << 16);
    float fb = __uint_as_float(hi2 & 0xFFFF0000u);
    float la = a - fa;
    float lb = b - fb;
    asm("cvt.rn.bf16x2.f32 %0, %1, %2;" : "=r"(lo2) : "f"(lb), "f"(la));
}

/* ===== prepass: x -> Xh/Xl [b][k]; w -> Wh/Wl transposed [n][k] ===== */
__global__ void __launch_bounds__(256)
prepass_kernel(const float* __restrict__ x, const float* __restrict__ w) {
    const int t = threadIdx.x;
    if (blockIdx.x < 1440) {
        /* w tile: c = bid/144, k0 = (bid%144)*64; transpose [64k][16o] -> [16n][64k] */
        const int c  = blockIdx.x / 144;
        const int k0 = (blockIdx.x % 144) * 64;
        __shared__ float tile[64][17];
        const float4* __restrict__ w4 = (const float4*)w;
        {
            int kk = t >> 2, o4 = t & 3;
            float4 v = w4[(size_t)(c * KDIM + k0 + kk) * 4 + o4];
            tile[kk][o4 * 4 + 0] = v.x;
            tile[kk][o4 * 4 + 1] = v.y;
            tile[kk][o4 * 4 + 2] = v.z;
            tile[kk][o4 * 4 + 3] = v.w;
        }
        __syncthreads();
        {
            int o = t >> 4, kg = t & 15;
            int n = c * 16 + o;
            float f0 = tile[kg * 4 + 0][o];
            float f1 = tile[kg * 4 + 1][o];
            float f2 = tile[kg * 4 + 2][o];
            float f3 = tile[kg * 4 + 3][o];
            uint32_t h0, l0, h1, l1;
            cvt_split2(f0, f1, h0, l0);
            cvt_split2(f2, f3, h1, l1);
            size_t ui = (size_t)n * (KDIM / 4) + (k0 >> 2) + kg;
            ((uint2*)g_Wh)[ui] = make_uint2(h0, h1);
            ((uint2*)g_Wl)[ui] = make_uint2(l0, l1);
        }
    } else {
        /* x: 589824 float4 over 768 blocks x 256 thr x 3 */
        const int xb = blockIdx.x - 1440;
        const float4* __restrict__ x4 = (const float4*)x;
        #pragma unroll
        for (int j = 0; j < 3; j++) {
            size_t idx = (size_t)xb * 768 + j * 256 + t;
            float4 v = x4[idx];
            uint32_t h0, l0, h1, l1;
            cvt_split2(v.x, v.y, h0, l0);
            cvt_split2(v.z, v.w, h1, l1);
            ((uint2*)g_Xh)[idx] = make_uint2(h0, h1);
            ((uint2*)g_Xl)[idx] = make_uint2(l0, l1);
        }
    }
}

/* ===== GEMM: pure cp.async + wmma 3-pass bf16-split, split-K ===== */
__global__ void __launch_bounds__(NTHR, 2)
gemm_kernel() {
    __shared__ __align__(16) __nv_bfloat16 Ah[2][128 * LDA];
    __shared__ __align__(16) __nv_bfloat16 Al[2][128 * LDA];
    __shared__ __align__(16) __nv_bfloat16 Bh[2][80 * LDA];
    __shared__ __align__(16) __nv_bfloat16 Bl[2][80 * LDA];

    const int tid  = threadIdx.x;
    const int warp = tid >> 5;
    const int ks   = blockIdx.x;
    const int nh   = blockIdx.y;
    const int mh   = blockIdx.z;
    const int kbase = ks * KPER;

    const uint32_t aAh[2] = {smem_u32(Ah[0]), smem_u32(Ah[1])};
    const uint32_t aAl[2] = {smem_u32(Al[0]), smem_u32(Al[1])};
    const uint32_t aBh[2] = {smem_u32(Bh[0]), smem_u32(Bh[1])};
    const uint32_t aBl[2] = {smem_u32(Bl[0]), smem_u32(Bl[1])};

    wmma::fragment<wmma::accumulator, 16, 16, 16, float> c[2][5];
    #pragma unroll
    for (int mt = 0; mt < 2; mt++)
        #pragma unroll
        for (int nt = 0; nt < 5; nt++) wmma::fill_fragment(c[mt][nt], 0.0f);

    auto issue_stage = [&](int s, int d) {
        const int k0 = kbase + s * KT;
        /* A: 512 x 16B units (Ah 256, Al 256) */
        #pragma unroll
        for (int j = 0; j < 4; j++) {
            int u = j * NTHR + tid;
            int arr  = u >> 8;
            int row  = (u & 255) >> 1;
            int half = u & 1;
            const __nv_bfloat16* src =
                (arr ? g_Xl : g_Xh) + (size_t)(mh * 128 + row) * KDIM + k0 + half * 8;
            uint32_t dst = (arr ? aAl[d] : aAh[d]) + (uint32_t)(row * LDA + half * 8) * 2;
            cp16(dst, src);
        }
        /* B: 320 x 16B units (Bh 160, Bl 160) */
        #pragma unroll
        for (int j = 0; j < 3; j++) {
            int u = j * NTHR + tid;
            if (u < 320) {
                int arr  = u >= 160;
                int rem  = arr ? (u - 160) : u;
                int row  = rem >> 1;
                int half = rem & 1;
                const __nv_bfloat16* src =
                    (arr ? g_Wl : g_Wh) + (size_t)(nh * 80 + row) * KDIM + k0 + half * 8;
                uint32_t dst = (arr ? aBl[d] : aBh[d]) + (uint32_t)(row * LDA + half * 8) * 2;
                cp16(dst, src);
            }
        }
    };

    issue_stage(0, 0); cp_commit();
    issue_stage(1, 1); cp_commit();

    const int m0 = warp * 32;

    #pragma unroll
    for (int s = 0; s < NSTG; s++) {
        const int d = s & 1;
        if (s < NSTG - 1) cp_wait1(); else cp_wait0();
        __syncthreads();

        {
            wmma::fragment<wmma::matrix_a, 16, 16, 16, __nv_bfloat16, wmma::row_major> ah0, ah1, al0, al1;
            wmma::load_matrix_sync(ah0, &Ah[d][m0 * LDA], LDA);
            wmma::load_matrix_sync(ah1, &Ah[d][(m0 + 16) * LDA], LDA);
            wmma::load_matrix_sync(al0, &Al[d][m0 * LDA], LDA);
            wmma::load_matrix_sync(al1, &Al[d][(m0 + 16) * LDA], LDA);
            wmma::fragment<wmma::matrix_b, 16, 16, 16, __nv_bfloat16, wmma::col_major> bh[5], bl[5];
            #pragma unroll
            for (int nt = 0; nt < 5; nt++) {
                wmma::load_matrix_sync(bh[nt], &Bh[d][nt * 16 * LDA], LDA);
                wmma::load_matrix_sync(bl[nt], &Bl[d][nt * 16 * LDA], LDA);
            }
            #pragma unroll
            for (int nt = 0; nt < 5; nt++) {
                wmma::mma_sync(c[0][nt], ah0, bh[nt], c[0][nt]);
                wmma::mma_sync(c[1][nt], ah1, bh[nt], c[1][nt]);
            }
            #pragma unroll
            for (int nt = 0; nt < 5; nt++) {
                wmma::mma_sync(c[0][nt], ah0, bl[nt], c[0][nt]);
                wmma::mma_sync(c[1][nt], ah1, bl[nt], c[1][nt]);
            }
            #pragma unroll
            for (int nt = 0; nt < 5; nt++) {
                wmma::mma_sync(c[0][nt], al0, bh[nt], c[0][nt]);
                wmma::mma_sync(c[1][nt], al1, bh[nt], c[1][nt]);
            }
        }
        __syncthreads();
        if (s + 2 < NSTG) { issue_stage(s + 2, d); cp_commit(); }
    }

    /* epilogue: partials [b][ks][n] */
    #pragma unroll
    for (int mt = 0; mt < 2; mt++)
        #pragma unroll
        for (int nt = 0; nt < 5; nt++)
            wmma::store_matrix_sync(
                g_Upart + (size_t)(mh * 128 + m0 + mt * 16) * PSTRIDE
                        + ks * NCOL + nh * 80 + nt * 16,
                c[mt][nt], PSTRIDE, wmma::mem_row_major);
}

/* ===== reduce: U2[b][n] = sum_ks partials; grid (b, half) ===== */
__global__ void __launch_bounds__(480)
reduce_kernel() {
    const int b = blockIdx.x >> 1;
    const int h = blockIdx.x & 1;
    const int t = threadIdx.x;

    __shared__ __align__(16) float4 red[24][20];

    const float4* __restrict__ src =
        (const float4*)(g_Upart + (size_t)b * PSTRIDE) + h * 20;
    float4 acc = make_float4(0.f, 0.f, 0.f, 0.f);
    #pragma unroll
    for (int j = 0; j < 3; j++) {
        int p = t + j * 480;
        float4 v = src[(p / 20) * 40 + (p % 20)];
        acc.x += v.x; acc.y += v.y; acc.z += v.z; acc.w += v.w;
    }
    red[t / 20][t % 20] = acc;
    __syncthreads();

    if (t < 80) {
        float s = 0.f;
        #pragma unroll
        for (int i = 0; i < 24; i++)
            s += ((const float*)&red[i][t >> 2])[t & 3];
        g_U2[(size_t)b * NCOL + h * 80 + t] = s;
    }
}

/* ===== routing: collapsed 3-iter dynamic routing on U2 ===== */
__global__ void __launch_bounds__(NCOL)
routing_kernel(float* __restrict__ out) {
    const int b  = blockIdx.x;
    const int tt = threadIdx.x;
    const int cc = tt >> 4;
    const int o  = tt & 15;

    const float u = g_U2[(size_t)b * NCOL + tt];

    __shared__ float L[NUM_C];
    if (tt < NUM_C) L[tt] = 0.f;
    __syncthreads();

    float v = 0.f;
    for (int it = 0; it < 3; it++) {
        float mx = L[0];
        #pragma unroll
        for (int j = 1; j < NUM_C; j++) mx = fmaxf(mx, L[j]);
        float den = 0.f;
        #pragma unroll
        for (int j = 0; j < NUM_C; j++) den += __expf(L[j] - mx);
        float p = __expf(L[cc] - mx) / den;

        float tv = p * u;
        v = tv * fabsf(tv) / (1.f + tv * tv);

        float S = v;
        S += __shfl_xor_sync(0xffffffffu, S, 8);
        S += __shfl_xor_sync(0xffffffffu, S, 4);
        S += __shfl_xor_sync(0xffffffffu, S, 2);
        S += __shfl_xor_sync(0xffffffffu, S, 1);

        __syncthreads();
        if (o == 0) L[cc] += p * S;
        __syncthreads();
    }
    out[(size_t)b * NCOL + tt] = v;
}

extern "C" void kernel_launch(void* const* d_in, const int* in_sizes, int n_in,
                              void* d_out, int out_size) {
    const float* x = (const float*)d_in[0];
    const float* w = (const float*)d_in[1];
    if (n_in >= 2 && in_sizes[0] == NUM_C * KDIM * OUT_CH) {
        w = (const float*)d_in[0];
        x = (const float*)d_in[1];
    }
    prepass_kernel<<<2208, 256>>>(x, w);
    gemm_kernel<<<dim3(KSPLIT, 2, 2), NTHR>>>();
    reduce_kernel<<<512, 480>>>();
    routing_kernel<<<BATCH, NCOL>>>((float*)d_out);
    (void)out_size;
}

// round 10
// speedup vs baseline: 1.1830x; 1.1830x over previous
#include <cuda_runtime.h>
#include <cuda_bf16.h>
#include <mma.h>
#include <cstdint>
#include <math.h>

using namespace nvcuda;

#define NUM_C   10
#define OUT_CH  16
#define BATCH   256
#define KDIM    9216
#define NCOL    160

#define KSPLIT  72
#define KPER    128
#define KT      16
#define NSTG    8
#define NTHR    128
#define LDA     24
#define PSTRIDE (KSPLIT * NCOL)    /* 11520 */

__device__ float g_Upart[BATCH * KSPLIT * NCOL];
__device__ __nv_bfloat16 g_Wh[NCOL * KDIM];
__device__ __nv_bfloat16 g_Wl[NCOL * KDIM];

__device__ __forceinline__ uint32_t smem_u32(const void* p) {
    uint32_t a;
    asm("{ .reg .u64 t; cvta.to.shared.u64 t, %1; cvt.u32.u64 %0, t; }"
        : "=r"(a) : "l"(p));
    return a;
}
__device__ __forceinline__ void cp16(uint32_t dst, const void* src) {
    asm volatile("cp.async.cg.shared.global [%0], [%1], 16;"
                 :: "r"(dst), "l"(src) : "memory");
}
__device__ __forceinline__ void cp_commit() {
    asm volatile("cp.async.commit_group;" ::: "memory");
}
__device__ __forceinline__ void cp_wait1() {
    asm volatile("cp.async.wait_group 1;" ::: "memory");
}
__device__ __forceinline__ void cp_wait0() {
    asm volatile("cp.async.wait_group 0;" ::: "memory");
}
/* packed fp32 -> bf16 hi/lo split */
__device__ __forceinline__ void cvt_split2(float a, float b,
                                           uint32_t& hi2, uint32_t& lo2) {
    asm("cvt.rn.bf16x2.f32 %0, %1, %2;" : "=r"(hi2) : "f"(b), "f"(a));
    float fa = __uint_as_float(hi2 << 16);
    float fb = __uint_as_float(hi2 & 0xFFFF0000u);
    float la = a - fa;
    float lb = b - fb;
    asm("cvt.rn.bf16x2.f32 %0, %1, %2;" : "=r"(lo2) : "f"(lb), "f"(la));
}

/* ===== prepass: w [10c][9216k][16o] -> Wh/Wl transposed [160n][9216k] ===== */
__global__ void __launch_bounds__(256)
prepass_kernel(const float* __restrict__ w) {
    const int t  = threadIdx.x;
    const int c  = blockIdx.x / 144;
    const int k0 = (blockIdx.x % 144) * 64;
    __shared__ float tile[64][17];
    const float4* __restrict__ w4 = (const float4*)w;
    {
        int kk = t >> 2, o4 = t & 3;
        float4 v = w4[(size_t)(c * KDIM + k0 + kk) * 4 + o4];
        tile[kk][o4 * 4 + 0] = v.x;
        tile[kk][o4 * 4 + 1] = v.y;
        tile[kk][o4 * 4 + 2] = v.z;
        tile[kk][o4 * 4 + 3] = v.w;
    }
    __syncthreads();
    {
        int o = t >> 4, kg = t & 15;
        int n = c * 16 + o;
        float f0 = tile[kg * 4 + 0][o];
        float f1 = tile[kg * 4 + 1][o];
        float f2 = tile[kg * 4 + 2][o];
        float f3 = tile[kg * 4 + 3][o];
        uint32_t h0, l0, h1, l1;
        cvt_split2(f0, f1, h0, l0);
        cvt_split2(f2, f3, h1, l1);
        size_t ui = (size_t)n * (KDIM / 4) + (k0 >> 2) + kg;
        ((uint2*)g_Wh)[ui] = make_uint2(h0, h1);
        ((uint2*)g_Wl)[ui] = make_uint2(l0, l1);
    }
}

/* ===== GEMM: inline-x-convert + cp.async B (triple buffer), 1 sync/stage ===== */
__global__ void __launch_bounds__(NTHR, 2)
gemm_kernel(const float* __restrict__ x) {
    __shared__ __align__(16) __nv_bfloat16 Ah[2][128 * LDA];
    __shared__ __align__(16) __nv_bfloat16 Al[2][128 * LDA];
    __shared__ __align__(16) __nv_bfloat16 Bh[3][80 * LDA];
    __shared__ __align__(16) __nv_bfloat16 Bl[3][80 * LDA];

    const int tid  = threadIdx.x;
    const int warp = tid >> 5;
    const int ks   = blockIdx.x;
    const int nh   = blockIdx.y;
    const int mh   = blockIdx.z;
    const int kbase = ks * KPER;

    const float4* __restrict__ x4 = (const float4*)x;

    const uint32_t aBh[3] = {smem_u32(Bh[0]), smem_u32(Bh[1]), smem_u32(Bh[2])};
    const uint32_t aBl[3] = {smem_u32(Bl[0]), smem_u32(Bl[1]), smem_u32(Bl[2])};

    wmma::fragment<wmma::accumulator, 16, 16, 16, float> c[2][5];
    #pragma unroll
    for (int mt = 0; mt < 2; mt++)
        #pragma unroll
        for (int nt = 0; nt < 5; nt++) wmma::fill_fragment(c[mt][nt], 0.0f);

    float4 rx[4];

    auto load_x = [&](int s) {
        const int k0 = kbase + s * KT;
        #pragma unroll
        for (int j = 0; j < 4; j++) {
            int fid = j * NTHR + tid;
            int row = fid >> 2, xq = fid & 3;
            rx[j] = x4[(size_t)(mh * 128 + row) * (KDIM / 4) + (k0 >> 2) + xq];
        }
    };
    auto convert_x = [&](int d) {
        #pragma unroll
        for (int j = 0; j < 4; j++) {
            int fid = j * NTHR + tid;
            int row = fid >> 2, xq = fid & 3;
            uint32_t h0, l0, h1, l1;
            cvt_split2(rx[j].x, rx[j].y, h0, l0);
            cvt_split2(rx[j].z, rx[j].w, h1, l1);
            *(uint2*)&Ah[d][row * LDA + xq * 4] = make_uint2(h0, h1);
            *(uint2*)&Al[d][row * LDA + xq * 4] = make_uint2(l0, l1);
        }
    };
    auto issue_b = [&](int s) {
        const int k0 = kbase + s * KT;
        const int d3 = s % 3;
        #pragma unroll
        for (int j = 0; j < 3; j++) {
            int u = j * NTHR + tid;
            if (u < 320) {
                int arr  = u >= 160;
                int rem  = u - arr * 160;
                int row  = rem >> 1;
                int half = rem & 1;
                const __nv_bfloat16* src =
                    (arr ? g_Wl : g_Wh) + (size_t)(nh * 80 + row) * KDIM + k0 + half * 8;
                uint32_t dst = (arr ? aBl[d3] : aBh[d3])
                             + (uint32_t)(row * LDA + half * 8) * 2;
                cp16(dst, src);
            }
        }
    };

    /* preamble */
    load_x(0);
    issue_b(0); cp_commit();
    issue_b(1); cp_commit();
    convert_x(0);
    load_x(1);
    __syncthreads();

    const int m0 = warp * 32;

    #pragma unroll
    for (int s = 0; s < NSTG; s++) {
        const int d  = s & 1;
        const int d3 = s % 3;
        if (s < NSTG - 1) cp_wait1(); else cp_wait0();
        __syncthreads();   /* B[d3] arrived; A[d] (written last stage) visible */

        {
            wmma::fragment<wmma::matrix_a, 16, 16, 16, __nv_bfloat16, wmma::row_major> ah0, ah1, al0, al1;
            wmma::load_matrix_sync(ah0, &Ah[d][m0 * LDA], LDA);
            wmma::load_matrix_sync(ah1, &Ah[d][(m0 + 16) * LDA], LDA);
            wmma::load_matrix_sync(al0, &Al[d][m0 * LDA], LDA);
            wmma::load_matrix_sync(al1, &Al[d][(m0 + 16) * LDA], LDA);
            wmma::fragment<wmma::matrix_b, 16, 16, 16, __nv_bfloat16, wmma::col_major> bh[5], bl[5];
            #pragma unroll
            for (int nt = 0; nt < 5; nt++) {
                wmma::load_matrix_sync(bh[nt], &Bh[d3][nt * 16 * LDA], LDA);
                wmma::load_matrix_sync(bl[nt], &Bl[d3][nt * 16 * LDA], LDA);
            }
            #pragma unroll
            for (int nt = 0; nt < 5; nt++) {
                wmma::mma_sync(c[0][nt], ah0, bh[nt], c[0][nt]);
                wmma::mma_sync(c[1][nt], ah1, bh[nt], c[1][nt]);
            }
            #pragma unroll
            for (int nt = 0; nt < 5; nt++) {
                wmma::mma_sync(c[0][nt], ah0, bl[nt], c[0][nt]);
                wmma::mma_sync(c[1][nt], ah1, bl[nt], c[1][nt]);
            }
            #pragma unroll
            for (int nt = 0; nt < 5; nt++) {
                wmma::mma_sync(c[0][nt], al0, bh[nt], c[0][nt]);
                wmma::mma_sync(c[1][nt], al1, bh[nt], c[1][nt]);
            }
        }

        /* fill next A buffer + prefetch; B for s+2 into third buffer (no race) */
        if (s + 1 < NSTG) {
            convert_x(d ^ 1);
            if (s + 2 < NSTG) {
                load_x(s + 2);
                issue_b(s + 2); cp_commit();
            }
        }
    }

    /* epilogue: partials [b][ks][n] */
    #pragma unroll
    for (int mt = 0; mt < 2; mt++)
        #pragma unroll
        for (int nt = 0; nt < 5; nt++)
            wmma::store_matrix_sync(
                g_Upart + (size_t)(mh * 128 + m0 + mt * 16) * PSTRIDE
                        + ks * NCOL + nh * 80 + nt * 16,
                c[mt][nt], PSTRIDE, wmma::mem_row_major);
}

/* ===== fused 72-way reduce (MLP-6 float4) + collapsed routing ===== */
__global__ void __launch_bounds__(512)
routing_kernel(float* __restrict__ out) {
    const int b = blockIdx.x;
    const int t = threadIdx.x;

    __shared__ __align__(16) float red[12][NCOL];
    __shared__ float L[NUM_C];

    if (t < 480) {
        const float4* src = (const float4*)(g_Upart + (size_t)b * PSTRIDE);
        float4 a0 = src[t];
        float4 a1 = src[t + 480];
        float4 a2 = src[t + 960];
        float4 a3 = src[t + 1440];
        float4 a4 = src[t + 1920];
        float4 a5 = src[t + 2400];
        float4 acc;
        acc.x = ((a0.x + a1.x) + (a2.x + a3.x)) + (a4.x + a5.x);
        acc.y = ((a0.y + a1.y) + (a2.y + a3.y)) + (a4.y + a5.y);
        acc.z = ((a0.z + a1.z) + (a2.z + a3.z)) + (a4.z + a5.z);
        acc.w = ((a0.w + a1.w) + (a2.w + a3.w)) + (a4.w + a5.w);
        *(float4*)&red[t / 40][(t % 40) * 4] = acc;
    }
    if (t < NUM_C) L[t] = 0.f;
    __syncthreads();

    const int cc = t >> 4;
    const int o  = t & 15;
    float u = 0.f, v = 0.f;
    if (t < NCOL) {
        float p0 = 0.f, p1 = 0.f, p2 = 0.f, p3 = 0.f;
        #pragma unroll
        for (int i = 0; i < 12; i += 4) {
            p0 += red[i][t];
            p1 += red[i + 1][t];
            p2 += red[i + 2][t];
            p3 += red[i + 3][t];
        }
        u = (p0 + p1) + (p2 + p3);
    }

    for (int it = 0; it < 3; it++) {
        float p = 0.f, S = 0.f;
        if (t < NCOL) {
            float mx = L[0];
            #pragma unroll
            for (int j = 1; j < NUM_C; j++) mx = fmaxf(mx, L[j]);
            float den = 0.f;
            #pragma unroll
            for (int j = 0; j < NUM_C; j++) den += __expf(L[j] - mx);
            p = __expf(L[cc] - mx) / den;

            float tv = p * u;
            v = tv * fabsf(tv) / (1.f + tv * tv);

            S = v;
            S += __shfl_xor_sync(0xffffffffu, S, 8);
            S += __shfl_xor_sync(0xffffffffu, S, 4);
            S += __shfl_xor_sync(0xffffffffu, S, 2);
            S += __shfl_xor_sync(0xffffffffu, S, 1);
        }
        __syncthreads();
        if (t < NCOL && o == 0) L[cc] += p * S;
        __syncthreads();
    }
    if (t < NCOL) out[(size_t)b * NCOL + t] = v;
}

extern "C" void kernel_launch(void* const* d_in, const int* in_sizes, int n_in,
                              void* d_out, int out_size) {
    const float* x = (const float*)d_in[0];
    const float* w = (const float*)d_in[1];
    if (n_in >= 2 && in_sizes[0] == NUM_C * KDIM * OUT_CH) {
        w = (const float*)d_in[0];
        x = (const float*)d_in[1];
    }
    prepass_kernel<<<1440, 256>>>(w);
    gemm_kernel<<<dim3(KSPLIT, 2, 2), NTHR>>>(x);
    routing_kernel<<<BATCH, 512>>>((float*)d_out);
    (void)out_size;
}

// round 11
// speedup vs baseline: 1.3011x; 1.0998x over previous
#include <cuda_runtime.h>
#include <cuda_bf16.h>
#include <mma.h>
#include <cstdint>
#include <math.h>

using namespace nvcuda;

#define NUM_C   10
#define OUT_CH  16
#define BATCH   256
#define KDIM    9216
#define NCOL    160

#define KSPLIT  72
#define KPER    128            /* K per block */
#define KT      16             /* K per stage */
#define NSTG    8
#define NTHR    128            /* 4 warps */
#define LDA     24             /* padded bf16 row (48B): LDSM conflict-free */
#define PSTRIDE (KSPLIT * NCOL)   /* 11520 */

/* partials: [b(256)][ks(72)][n(160)] — per-b contiguous for routing */
__device__ float g_Upart[BATCH * KSPLIT * NCOL];

/* packed fp32 -> bf16 hi/lo split */
__device__ __forceinline__ void cvt_split2(float a, float b,
                                           uint32_t& hi2, uint32_t& lo2) {
    asm("cvt.rn.bf16x2.f32 %0, %1, %2;" : "=r"(hi2) : "f"(b), "f"(a));
    float fa = __uint_as_float(hi2 << 16);
    float fb = __uint_as_float(hi2 & 0xFFFF0000u);
    float la = a - fa;
    float lb = b - fb;
    asm("cvt.rn.bf16x2.f32 %0, %1, %2;" : "=r"(lo2) : "f"(lb), "f"(la));
}

/* ============ GEMM: pipelined 3-pass bf16-split wmma, split-K ============ */
__global__ void __launch_bounds__(NTHR, 2)
gemm_kernel(const float* __restrict__ x, const float* __restrict__ w) {
    __shared__ __align__(16) __nv_bfloat16 Ah[2][128 * LDA];
    __shared__ __align__(16) __nv_bfloat16 Al[2][128 * LDA];
    __shared__ __align__(16) __nv_bfloat16 Bh[2][80 * LDA];
    __shared__ __align__(16) __nv_bfloat16 Bl[2][80 * LDA];

    const int tid  = threadIdx.x;
    const int warp = tid >> 5;
    const int ks   = blockIdx.x;
    const int nh   = blockIdx.y;
    const int mh   = blockIdx.z;
    const int kbase = ks * KPER;

    const float4* __restrict__ x4 = (const float4*)x;
    const float4* __restrict__ w4 = (const float4*)w;

    wmma::fragment<wmma::accumulator, 16, 16, 16, float> c[2][5];
    #pragma unroll
    for (int mt = 0; mt < 2; mt++)
        #pragma unroll
        for (int nt = 0; nt < 5; nt++) wmma::fill_fragment(c[mt][nt], 0.0f);

    float4 rx[4], rw[3];

    auto load_regs = [&](int k0) {
        #pragma unroll
        for (int j = 0; j < 4; j++) {
            int fid = j * NTHR + tid;
            int row = fid >> 2, xq = fid & 3;
            rx[j] = x4[(size_t)(mh * 128 + row) * (KDIM / 4) + (k0 >> 2) + xq];
        }
        #pragma unroll
        for (int j = 0; j < 3; j++) {
            if (j < 2 || tid < 64) {
                int fid = j * NTHR + tid;
                int cl = fid >> 6, rem = fid & 63;
                rw[j] = w4[((size_t)(nh * 5 + cl) * KDIM + k0 + (rem >> 2)) * 4 + (rem & 3)];
            }
        }
    };

    auto convert_store = [&](int d) {
        #pragma unroll
        for (int j = 0; j < 4; j++) {
            int fid = j * NTHR + tid;
            int row = fid >> 2, xq = fid & 3;
            uint32_t h0, l0, h1, l1;
            cvt_split2(rx[j].x, rx[j].y, h0, l0);
            cvt_split2(rx[j].z, rx[j].w, h1, l1);
            *(uint2*)&Ah[d][row * LDA + xq * 4] = make_uint2(h0, h1);
            *(uint2*)&Al[d][row * LDA + xq * 4] = make_uint2(l0, l1);
        }
        #pragma unroll
        for (int j = 0; j < 3; j++) {
            if (j < 2 || tid < 64) {
                int fid = j * NTHR + tid;
                int cl = fid >> 6, rem = fid & 63;
                int kloc = rem >> 2, o4 = rem & 3;
                int n0 = cl * 16 + o4 * 4;
                uint32_t hA, lA, hB, lB;
                cvt_split2(rw[j].x, rw[j].y, hA, lA);
                cvt_split2(rw[j].z, rw[j].w, hB, lB);
                uint16_t* bh = (uint16_t*)Bh[d];
                uint16_t* bl = (uint16_t*)Bl[d];
                bh[(n0 + 0) * LDA + kloc] = (uint16_t)(hA & 0xFFFFu);
                bh[(n0 + 1) * LDA + kloc] = (uint16_t)(hA >> 16);
                bh[(n0 + 2) * LDA + kloc] = (uint16_t)(hB & 0xFFFFu);
                bh[(n0 + 3) * LDA + kloc] = (uint16_t)(hB >> 16);
                bl[(n0 + 0) * LDA + kloc] = (uint16_t)(lA & 0xFFFFu);
                bl[(n0 + 1) * LDA + kloc] = (uint16_t)(lA >> 16);
                bl[(n0 + 2) * LDA + kloc] = (uint16_t)(lB & 0xFFFFu);
                bl[(n0 + 3) * LDA + kloc] = (uint16_t)(lB >> 16);
            }
        }
    };

    /* preamble: stage0 -> buf0, prefetch stage1 regs */
    load_regs(kbase);
    convert_store(0);
    load_regs(kbase + KT);
    __syncthreads();

    const int m0 = warp * 32;

    #pragma unroll
    for (int s = 0; s < NSTG; s++) {
        const int d = s & 1;
        {
            wmma::fragment<wmma::matrix_a, 16, 16, 16, __nv_bfloat16, wmma::row_major> ah0, ah1, al0, al1;
            wmma::load_matrix_sync(ah0, &Ah[d][m0 * LDA], LDA);
            wmma::load_matrix_sync(ah1, &Ah[d][(m0 + 16) * LDA], LDA);
            wmma::load_matrix_sync(al0, &Al[d][m0 * LDA], LDA);
            wmma::load_matrix_sync(al1, &Al[d][(m0 + 16) * LDA], LDA);
            wmma::fragment<wmma::matrix_b, 16, 16, 16, __nv_bfloat16, wmma::col_major> bh[5], bl[5];
            #pragma unroll
            for (int nt = 0; nt < 5; nt++) {
                wmma::load_matrix_sync(bh[nt], &Bh[d][nt * 16 * LDA], LDA);
                wmma::load_matrix_sync(bl[nt], &Bl[d][nt * 16 * LDA], LDA);
            }
            #pragma unroll
            for (int nt = 0; nt < 5; nt++) {
                wmma::mma_sync(c[0][nt], ah0, bh[nt], c[0][nt]);
                wmma::mma_sync(c[1][nt], ah1, bh[nt], c[1][nt]);
            }
            #pragma unroll
            for (int nt = 0; nt < 5; nt++) {
                wmma::mma_sync(c[0][nt], ah0, bl[nt], c[0][nt]);
                wmma::mma_sync(c[1][nt], ah1, bl[nt], c[1][nt]);
            }
            #pragma unroll
            for (int nt = 0; nt < 5; nt++) {
                wmma::mma_sync(c[0][nt], al0, bh[nt], c[0][nt]);
                wmma::mma_sync(c[1][nt], al1, bh[nt], c[1][nt]);
            }
        }
        if (s + 1 < NSTG) {
            convert_store(d ^ 1);
            if (s + 2 < NSTG) load_regs(kbase + (s + 2) * KT);
        }
        __syncthreads();
    }

    /* epilogue: partials [b][ks][n] */
    #pragma unroll
    for (int mt = 0; mt < 2; mt++)
        #pragma unroll
        for (int nt = 0; nt < 5; nt++)
            wmma::store_matrix_sync(
                g_Upart + (size_t)(mh * 128 + m0 + mt * 16) * PSTRIDE
                        + ks * NCOL + nh * 80 + nt * 16,
                c[mt][nt], PSTRIDE, wmma::mem_row_major);
}

/* ===== fused 72-way reduce (MLP-6 float4) + collapsed routing ===== */
__global__ void __launch_bounds__(512)
routing_kernel(float* __restrict__ out) {
    const int b = blockIdx.x;
    const int t = threadIdx.x;

    __shared__ __align__(16) float red[12][NCOL];
    __shared__ float L[NUM_C];

    if (t < 480) {
        const float4* src = (const float4*)(g_Upart + (size_t)b * PSTRIDE);
        float4 a0 = src[t];
        float4 a1 = src[t + 480];
        float4 a2 = src[t + 960];
        float4 a3 = src[t + 1440];
        float4 a4 = src[t + 1920];
        float4 a5 = src[t + 2400];
        float4 acc;
        acc.x = ((a0.x + a1.x) + (a2.x + a3.x)) + (a4.x + a5.x);
        acc.y = ((a0.y + a1.y) + (a2.y + a3.y)) + (a4.y + a5.y);
        acc.z = ((a0.z + a1.z) + (a2.z + a3.z)) + (a4.z + a5.z);
        acc.w = ((a0.w + a1.w) + (a2.w + a3.w)) + (a4.w + a5.w);
        *(float4*)&red[t / 40][(t % 40) * 4] = acc;
    }
    if (t < NUM_C) L[t] = 0.f;
    __syncthreads();

    const int cc = t >> 4;
    const int o  = t & 15;
    float u = 0.f, v = 0.f;
    if (t < NCOL) {
        float p0 = 0.f, p1 = 0.f, p2 = 0.f, p3 = 0.f;
        #pragma unroll
        for (int i = 0; i < 12; i += 4) {
            p0 += red[i][t];
            p1 += red[i + 1][t];
            p2 += red[i + 2][t];
            p3 += red[i + 3][t];
        }
        u = (p0 + p1) + (p2 + p3);
    }

    for (int it = 0; it < 3; it++) {
        float p = 0.f, S = 0.f;
        if (t < NCOL) {
            float mx = L[0];
            #pragma unroll
            for (int j = 1; j < NUM_C; j++) mx = fmaxf(mx, L[j]);
            float den = 0.f;
            #pragma unroll
            for (int j = 0; j < NUM_C; j++) den += __expf(L[j] - mx);
            p = __expf(L[cc] - mx) / den;

            float tv = p * u;
            v = tv * fabsf(tv) / (1.f + tv * tv);

            S = v;
            S += __shfl_xor_sync(0xffffffffu, S, 8);
            S += __shfl_xor_sync(0xffffffffu, S, 4);
            S += __shfl_xor_sync(0xffffffffu, S, 2);
            S += __shfl_xor_sync(0xffffffffu, S, 1);
        }
        __syncthreads();
        if (t < NCOL && o == 0) L[cc] += p * S;
        __syncthreads();
    }
    if (t < NCOL) out[(size_t)b * NCOL + t] = v;
}

extern "C" void kernel_launch(void* const* d_in, const int* in_sizes, int n_in,
                              void* d_out, int out_size) {
    const float* x = (const float*)d_in[0];
    const float* w = (const float*)d_in[1];
    if (n_in >= 2 && in_sizes[0] == NUM_C * KDIM * OUT_CH) {
        w = (const float*)d_in[0];
        x = (const float*)d_in[1];
    }
    gemm_kernel<<<dim3(KSPLIT, 2, 2), NTHR>>>(x, w);
    routing_kernel<<<BATCH, 512>>>((float*)d_out);
    (void)out_size;
}